// round 4
// baseline (speedup 1.0000x reference)
#include <cuda_runtime.h>
#include <cuda_bf16.h>

#define T_DIM 4096
#define H_DIM 2048
#define I_DIM 2048
#define E_NUM 16

typedef unsigned long long ull;

// ---------------- static scratch (no allocations allowed) ----------------
__device__ int   d_ids[2 * T_DIM];
__device__ float d_wts[2 * T_DIM];
__device__ int   d_counts[E_NUM];
__device__ int   d_offs[E_NUM + 1];
__device__ int   d_tok[2 * T_DIM];
__device__ int   d_slots[2 * T_DIM];
__device__ float d_h[(size_t)2 * T_DIM * I_DIM];   // 64 MB
__device__ float d_y[(size_t)2 * T_DIM * H_DIM];   // 64 MB

// ---------------- packed f32x2 helpers (Blackwell FFMA2) ----------------
__device__ __forceinline__ ull fma2(ull a, ull b, ull c) {
    ull d;
    asm("fma.rn.f32x2 %0, %1, %2, %3;" : "=l"(d) : "l"(a), "l"(b), "l"(c));
    return d;
}
__device__ __forceinline__ ull pack2(float x, float y) {
    ull d;
    asm("mov.b64 %0, {%1, %2};" : "=l"(d) : "f"(x), "f"(y));
    return d;
}
__device__ __forceinline__ float2 unpack2(ull v) {
    float2 r;
    asm("mov.b64 {%0, %1}, %2;" : "=f"(r.x), "=f"(r.y) : "l"(v));
    return r;
}

// ---------------- 1. gating: logits -> softmax -> top2 -> renorm ----------------
__global__ void gate_kernel(const float* __restrict__ x, const float* __restrict__ gw) {
    int t = blockIdx.x;
    int lane = threadIdx.x & 31;
    int w = threadIdx.x >> 5;      // 4 warps, 4 experts each
    const float* xr = x + (size_t)t * H_DIM;
    const float* g0 = gw + (size_t)(w * 4) * H_DIM;
    float acc0 = 0.f, acc1 = 0.f, acc2 = 0.f, acc3 = 0.f;
    for (int k = lane; k < H_DIM; k += 32) {
        float xv = xr[k];
        acc0 += xv * g0[k];
        acc1 += xv * g0[H_DIM + k];
        acc2 += xv * g0[2 * H_DIM + k];
        acc3 += xv * g0[3 * H_DIM + k];
    }
    __shared__ float sl[16];
    float accs[4] = {acc0, acc1, acc2, acc3};
#pragma unroll
    for (int j = 0; j < 4; j++) {
        float v = accs[j];
#pragma unroll
        for (int o = 16; o; o >>= 1) v += __shfl_xor_sync(0xffffffff, v, o);
        if (lane == 0) sl[w * 4 + j] = v;
    }
    __syncthreads();
    if (threadIdx.x == 0) {
        float mx = sl[0];
#pragma unroll
        for (int i = 1; i < 16; i++) mx = fmaxf(mx, sl[i]);
        float ex[16];
#pragma unroll
        for (int i = 0; i < 16; i++) ex[i] = expf(sl[i] - mx);
        int b0 = 0;
#pragma unroll
        for (int i = 1; i < 16; i++) if (sl[i] > sl[b0]) b0 = i;  // ties -> lowest idx (jax top_k)
        int b1 = -1;
#pragma unroll
        for (int i = 0; i < 16; i++) {
            if (i == b0) continue;
            if (b1 < 0 || sl[i] > sl[b1]) b1 = i;
        }
        float s = ex[b0] + ex[b1];
        d_ids[2 * t] = b0;
        d_ids[2 * t + 1] = b1;
        d_wts[2 * t] = ex[b0] / s;
        d_wts[2 * t + 1] = ex[b1] / s;
    }
}

// ---------------- 2. build per-expert token lists (deterministic warp scan) ----------------
__global__ void count_kernel() {
    int e = blockIdx.x, lane = threadIdx.x;
    int cnt = 0;
    for (int base = 0; base < T_DIM; base += 32) {
        int t = base + lane;
        bool p = (d_ids[2 * t] == e) || (d_ids[2 * t + 1] == e);
        unsigned b = __ballot_sync(0xffffffff, p);
        cnt += __popc(b);
    }
    if (lane == 0) d_counts[e] = cnt;
}

__global__ void offs_kernel() {
    int s = 0;
    for (int e = 0; e < E_NUM; e++) { d_offs[e] = s; s += d_counts[e]; }
    d_offs[E_NUM] = s;   // == 2*T always
}

__global__ void fill_kernel() {
    int e = blockIdx.x, lane = threadIdx.x;
    int pos = d_offs[e];
    for (int base = 0; base < T_DIM; base += 32) {
        int t = base + lane;
        int k = (d_ids[2 * t] == e) ? 0 : ((d_ids[2 * t + 1] == e) ? 1 : -1);
        unsigned b = __ballot_sync(0xffffffff, k >= 0);
        if (k >= 0) {
            int idx = pos + __popc(b & ((1u << lane) - 1u));
            d_tok[idx] = t;
            d_slots[2 * t + k] = idx;
        }
        pos += __popc(b);
    }
}

// ---------------- 3. GEMM1 + SiLU*U fused: h = silu(x@Wg^T) * (x@Wu^T) ----------------
// grid (mtiles=64, I/64=32, E). BM=64, BN=64 (paired G/U tiles), BK=16.
// 256 threads, thread tile 4 rows x 4 cols per G and U, packed f32x2 over col pairs.
__global__ void __launch_bounds__(256) gemm1_kernel(const float* __restrict__ x,
                                                    const float* __restrict__ ws) {
    int e = blockIdx.z;
    int cnt = d_counts[e];
    int mbase = blockIdx.x * 64;
    if (mbase >= cnt) return;
    int off = d_offs[e];
    int nbase = blockIdx.y * 64;

    __shared__ __align__(16) float As[16][68];
    __shared__ __align__(16) float Bg[16][68];
    __shared__ __align__(16) float Bu[16][68];

    int tid = threadIdx.x;
    int tx = tid & 15, ty = tid >> 4;
    int lk = tid & 15, lr0 = tid >> 4;

    const float* wsG = ws + (size_t)e * (2 * I_DIM) * H_DIM + (size_t)nbase * H_DIM;
    const float* wsU = wsG + (size_t)I_DIM * H_DIM;

    int tokr[4];
#pragma unroll
    for (int i = 0; i < 4; i++) {
        int m = lr0 + 16 * i;
        tokr[i] = (mbase + m < cnt) ? d_tok[off + mbase + m] : -1;
    }

    ull accG[4][2], accU[4][2];
#pragma unroll
    for (int i = 0; i < 4; i++)
#pragma unroll
        for (int j = 0; j < 2; j++) { accG[i][j] = 0ull; accU[i][j] = 0ull; }

    for (int k0 = 0; k0 < H_DIM; k0 += 16) {
#pragma unroll
        for (int i = 0; i < 4; i++) {
            int m = lr0 + 16 * i;
            As[lk][m] = (tokr[i] >= 0) ? x[(size_t)tokr[i] * H_DIM + k0 + lk] : 0.f;
            Bg[lk][m] = wsG[(size_t)m * H_DIM + k0 + lk];
            Bu[lk][m] = wsU[(size_t)m * H_DIM + k0 + lk];
        }
        __syncthreads();
#pragma unroll
        for (int kk = 0; kk < 16; kk++) {
            ull bg0 = *(const ull*)&Bg[kk][tx * 4];
            ull bg1 = *(const ull*)&Bg[kk][tx * 4 + 2];
            ull bu0 = *(const ull*)&Bu[kk][tx * 4];
            ull bu1 = *(const ull*)&Bu[kk][tx * 4 + 2];
#pragma unroll
            for (int i = 0; i < 4; i++) {
                float a = As[kk][ty * 4 + i];
                ull ap = pack2(a, a);
                accG[i][0] = fma2(ap, bg0, accG[i][0]);
                accG[i][1] = fma2(ap, bg1, accG[i][1]);
                accU[i][0] = fma2(ap, bu0, accU[i][0]);
                accU[i][1] = fma2(ap, bu1, accU[i][1]);
            }
        }
        __syncthreads();
    }

#pragma unroll
    for (int i = 0; i < 4; i++) {
        int m = mbase + ty * 4 + i;
        if (m >= cnt) continue;
        size_t row = (size_t)(off + m) * I_DIM;
#pragma unroll
        for (int jp = 0; jp < 2; jp++) {
            float2 g2 = unpack2(accG[i][jp]);
            float2 u2 = unpack2(accU[i][jp]);
            int col = nbase + tx * 4 + 2 * jp;
            float h0 = u2.x * g2.x / (1.f + expf(-g2.x));
            float h1 = u2.y * g2.y / (1.f + expf(-g2.y));
            d_h[row + col] = h0;
            d_h[row + col + 1] = h1;
        }
    }
}

// ---------------- 4. GEMM2: y = h @ W2^T ----------------
// grid (mtiles=64, H/128=16, E). BM=64, BN=128, BK=16. 256 threads, thread tile 4x8.
__global__ void __launch_bounds__(256) gemm2_kernel(const float* __restrict__ w2s) {
    int e = blockIdx.z;
    int cnt = d_counts[e];
    int mbase = blockIdx.x * 64;
    if (mbase >= cnt) return;
    int off = d_offs[e];
    int nbase = blockIdx.y * 128;

    __shared__ __align__(16) float As[16][68];
    __shared__ __align__(16) float Bs[16][132];

    int tid = threadIdx.x;
    int tx = tid & 15, ty = tid >> 4;
    int lk = tid & 15, lr0 = tid >> 4;

    const float* w2 = w2s + (size_t)e * H_DIM * I_DIM + (size_t)nbase * I_DIM;

    ull acc[4][4];
#pragma unroll
    for (int i = 0; i < 4; i++)
#pragma unroll
        for (int j = 0; j < 4; j++) acc[i][j] = 0ull;

    for (int k0 = 0; k0 < I_DIM; k0 += 16) {
#pragma unroll
        for (int i = 0; i < 4; i++) {
            int m = lr0 + 16 * i;
            As[lk][m] = (mbase + m < cnt) ? d_h[(size_t)(off + mbase + m) * I_DIM + k0 + lk] : 0.f;
        }
#pragma unroll
        for (int i = 0; i < 8; i++) {
            int n = lr0 + 16 * i;
            Bs[lk][n] = w2[(size_t)n * I_DIM + k0 + lk];
        }
        __syncthreads();
#pragma unroll
        for (int kk = 0; kk < 16; kk++) {
            ull b0 = *(const ull*)&Bs[kk][tx * 8];
            ull b1 = *(const ull*)&Bs[kk][tx * 8 + 2];
            ull b2 = *(const ull*)&Bs[kk][tx * 8 + 4];
            ull b3 = *(const ull*)&Bs[kk][tx * 8 + 6];
#pragma unroll
            for (int i = 0; i < 4; i++) {
                float a = As[kk][ty * 4 + i];
                ull ap = pack2(a, a);
                acc[i][0] = fma2(ap, b0, acc[i][0]);
                acc[i][1] = fma2(ap, b1, acc[i][1]);
                acc[i][2] = fma2(ap, b2, acc[i][2]);
                acc[i][3] = fma2(ap, b3, acc[i][3]);
            }
        }
        __syncthreads();
    }

#pragma unroll
    for (int i = 0; i < 4; i++) {
        int m = mbase + ty * 4 + i;
        if (m >= cnt) continue;
        size_t row = (size_t)(off + m) * H_DIM;
#pragma unroll
        for (int jp = 0; jp < 4; jp++) {
            float2 v = unpack2(acc[i][jp]);
            int col = nbase + tx * 8 + 2 * jp;
            d_y[row + col] = v.x;
            d_y[row + col + 1] = v.y;
        }
    }
}

// ---------------- 5. deterministic combine: out[t] = w0*y[slot0] + w1*y[slot1] ----------------
__global__ void combine_kernel(float* __restrict__ out) {
    int idx = blockIdx.x * blockDim.x + threadIdx.x;   // < T*H
    int t = idx >> 11;          // H = 2048
    int c = idx & 2047;
    float w0 = d_wts[2 * t], w1 = d_wts[2 * t + 1];
    int s0 = d_slots[2 * t], s1 = d_slots[2 * t + 1];
    out[idx] = w0 * d_y[(size_t)s0 * H_DIM + c] + w1 * d_y[(size_t)s1 * H_DIM + c];
}

// ---------------- launch ----------------
extern "C" void kernel_launch(void* const* d_in, const int* in_sizes, int n_in,
                              void* d_out, int out_size) {
    const float* x    = (const float*)d_in[0];
    const float* gw   = (const float*)d_in[1];
    const float* ws   = (const float*)d_in[2];
    const float* w2s  = (const float*)d_in[3];
    // d_in[4] = top_k, fixed at 2 for this problem
    float* out = (float*)d_out;

    gate_kernel<<<T_DIM, 128>>>(x, gw);
    count_kernel<<<E_NUM, 32>>>();
    offs_kernel<<<1, 1>>>();
    fill_kernel<<<E_NUM, 32>>>();

    dim3 g1(T_DIM / 64, I_DIM / 64, E_NUM);   // (64, 32, 16)
    gemm1_kernel<<<g1, 256>>>(x, ws);

    dim3 g2(T_DIM / 64, H_DIM / 128, E_NUM);  // (64, 16, 16)
    gemm2_kernel<<<g2, 256>>>(w2s);

    combine_kernel<<<(T_DIM * H_DIM) / 256, 256>>>(out);
}

// round 7
// speedup vs baseline: 1.8948x; 1.8948x over previous
#include <cuda_runtime.h>
#include <cuda_fp16.h>
#include <cstdint>

#define T_DIM 4096
#define H_DIM 2048
#define I_DIM 2048
#define E_NUM 16

typedef unsigned long long ull;

// ---------------- static scratch (no allocations allowed) ----------------
__device__ int   d_ids[2 * T_DIM];
__device__ float d_wts[2 * T_DIM];
__device__ int   d_counts[E_NUM];
__device__ int   d_offs[E_NUM + 1];
__device__ int   d_tok[2 * T_DIM];
__device__ int   d_slots[2 * T_DIM];
__device__ float d_h[(size_t)2 * T_DIM * I_DIM];   // 64 MB
__device__ float d_y[(size_t)2 * T_DIM * H_DIM];   // 64 MB

// ---------------- GEMM config ----------------
#define BK 32
#define STRIDE 40                       // halfs per smem row (pad 8 -> conflict-free frags)
#define OFF_AH 0
#define OFF_AL (128 * STRIDE)
#define OFF_BH (2 * 128 * STRIDE)
#define OFF_BL (3 * 128 * STRIDE)
#define STG_HALF (4 * 128 * STRIDE)     // 20480 halfs per stage
#define SMEM_BYTES (2 * STG_HALF * 2)   // 81920 B double-buffered

// mma.sync m16n8k16 fp16 inputs, fp32 accumulate (legacy tensor path, valid on compute_103)
#define MMA16816(d, a, b0, b1)                                              \
    asm volatile(                                                           \
        "mma.sync.aligned.m16n8k16.row.col.f32.f16.f16.f32 "                \
        "{%0,%1,%2,%3}, {%4,%5,%6,%7}, {%8,%9}, {%0,%1,%2,%3};"             \
        : "+f"((d)[0]), "+f"((d)[1]), "+f"((d)[2]), "+f"((d)[3])            \
        : "r"((a)[0]), "r"((a)[1]), "r"((a)[2]), "r"((a)[3]),               \
          "r"(b0), "r"(b1))

// split fp32 pair -> packed fp16 hi + packed fp16 lo (a = hi + lo to ~2^-22)
__device__ __forceinline__ uint32_t pack_hl(float x, float y, uint32_t& lo) {
    __half hx = __float2half_rn(x), hy = __float2half_rn(y);
    __half lx = __float2half_rn(x - __half2float(hx));
    __half ly = __float2half_rn(y - __half2float(hy));
    lo = ((uint32_t)__half_as_ushort(ly) << 16) | (uint32_t)__half_as_ushort(lx);
    return ((uint32_t)__half_as_ushort(hy) << 16) | (uint32_t)__half_as_ushort(hx);
}

// 16 floats (4 float4) -> 16 hi halfs + 16 lo halfs in smem
__device__ __forceinline__ void sts_split(__half* dst_hi, __half* dst_lo, const float4* v) {
    uint32_t hi[8], lo[8];
#pragma unroll
    for (int q = 0; q < 4; q++) {
        hi[2 * q]     = pack_hl(v[q].x, v[q].y, lo[2 * q]);
        hi[2 * q + 1] = pack_hl(v[q].z, v[q].w, lo[2 * q + 1]);
    }
    *(uint4*)(dst_hi)     = make_uint4(hi[0], hi[1], hi[2], hi[3]);
    *(uint4*)(dst_hi + 8) = make_uint4(hi[4], hi[5], hi[6], hi[7]);
    *(uint4*)(dst_lo)     = make_uint4(lo[0], lo[1], lo[2], lo[3]);
    *(uint4*)(dst_lo + 8) = make_uint4(lo[4], lo[5], lo[6], lo[7]);
}

// ---------------- 1. gating ----------------
__global__ void gate_kernel(const float* __restrict__ x, const float* __restrict__ gw) {
    int t = blockIdx.x;
    int lane = threadIdx.x & 31;
    int w = threadIdx.x >> 5;
    const float* xr = x + (size_t)t * H_DIM;
    const float* g0 = gw + (size_t)(w * 4) * H_DIM;
    float acc0 = 0.f, acc1 = 0.f, acc2 = 0.f, acc3 = 0.f;
    for (int k = lane; k < H_DIM; k += 32) {
        float xv = xr[k];
        acc0 += xv * g0[k];
        acc1 += xv * g0[H_DIM + k];
        acc2 += xv * g0[2 * H_DIM + k];
        acc3 += xv * g0[3 * H_DIM + k];
    }
    __shared__ float sl[16];
    float accs[4] = {acc0, acc1, acc2, acc3};
#pragma unroll
    for (int j = 0; j < 4; j++) {
        float v = accs[j];
#pragma unroll
        for (int o = 16; o; o >>= 1) v += __shfl_xor_sync(0xffffffff, v, o);
        if (lane == 0) sl[w * 4 + j] = v;
    }
    __syncthreads();
    if (threadIdx.x == 0) {
        float mx = sl[0];
#pragma unroll
        for (int i = 1; i < 16; i++) mx = fmaxf(mx, sl[i]);
        float ex[16];
#pragma unroll
        for (int i = 0; i < 16; i++) ex[i] = expf(sl[i] - mx);
        int b0 = 0;
#pragma unroll
        for (int i = 1; i < 16; i++) if (sl[i] > sl[b0]) b0 = i;
        int b1 = -1;
#pragma unroll
        for (int i = 0; i < 16; i++) {
            if (i == b0) continue;
            if (b1 < 0 || sl[i] > sl[b1]) b1 = i;
        }
        float s = ex[b0] + ex[b1];
        d_ids[2 * t] = b0;
        d_ids[2 * t + 1] = b1;
        d_wts[2 * t] = ex[b0] / s;
        d_wts[2 * t + 1] = ex[b1] / s;
    }
}

// ---------------- 2. routing (parallel segmented scans, deterministic) ----------------
__global__ void count_kernel() {
    int e = blockIdx.x;
    int w = threadIdx.x >> 5, lane = threadIdx.x & 31;
    __shared__ int wcnt[8];
    int cnt = 0;
#pragma unroll
    for (int i = 0; i < 16; i++) {
        int t = w * 512 + i * 32 + lane;
        bool p = (d_ids[2 * t] == e) || (d_ids[2 * t + 1] == e);
        cnt += __popc(__ballot_sync(0xffffffff, p));
    }
    if (lane == 0) wcnt[w] = cnt;
    __syncthreads();
    if (threadIdx.x == 0) {
        int s = 0;
#pragma unroll
        for (int i = 0; i < 8; i++) s += wcnt[i];
        d_counts[e] = s;
    }
}

__global__ void offs_kernel() {
    int s = 0;
    for (int e = 0; e < E_NUM; e++) { d_offs[e] = s; s += d_counts[e]; }
    d_offs[E_NUM] = s;
}

__global__ void fill_kernel() {
    int e = blockIdx.x;
    int w = threadIdx.x >> 5, lane = threadIdx.x & 31;
    __shared__ int wcnt[8], woff[8];
    int cnt = 0;
#pragma unroll
    for (int i = 0; i < 16; i++) {
        int t = w * 512 + i * 32 + lane;
        bool p = (d_ids[2 * t] == e) || (d_ids[2 * t + 1] == e);
        cnt += __popc(__ballot_sync(0xffffffff, p));
    }
    if (lane == 0) wcnt[w] = cnt;
    __syncthreads();
    if (threadIdx.x == 0) {
        int s = 0;
#pragma unroll
        for (int i = 0; i < 8; i++) { woff[i] = s; s += wcnt[i]; }
    }
    __syncthreads();
    int pos = d_offs[e] + woff[w];
#pragma unroll
    for (int i = 0; i < 16; i++) {
        int t = w * 512 + i * 32 + lane;
        int k = (d_ids[2 * t] == e) ? 0 : ((d_ids[2 * t + 1] == e) ? 1 : -1);
        unsigned b = __ballot_sync(0xffffffff, k >= 0);
        if (k >= 0) {
            int idx = pos + __popc(b & ((1u << lane) - 1u));
            d_tok[idx] = t;
            d_slots[2 * t + k] = idx;
        }
        pos += __popc(b);
    }
}

// =========== fragment loads (conflict-free with STRIDE=40) ===========
__device__ __forceinline__ void ld_afrag(uint32_t* f, const __half* p) {
    f[0] = *(const uint32_t*)p;
    f[1] = *(const uint32_t*)(p + 8 * STRIDE);
    f[2] = *(const uint32_t*)(p + 8);
    f[3] = *(const uint32_t*)(p + 8 * STRIDE + 8);
}

// ---------------- 3. GEMM1 + fused SiLU*U ----------------
// grid (32, I/64, E). BM=128 tokens, B rows: group g=row>>5,r=row&31:
//   icol = n0 + (g>>1)*32 + r ; g&1 ? up : gate  -> warp wn holds matching g/u pairs.
__global__ void __launch_bounds__(256, 1) gemm1_kernel(const float* __restrict__ x,
                                                       const float* __restrict__ ws) {
    int e = blockIdx.z;
    int cnt = d_counts[e];
    int mbase = blockIdx.x * 128;
    if (mbase >= cnt) return;
    int off = d_offs[e];
    int n0 = blockIdx.y * 64;

    extern __shared__ __align__(16) __half sm[];

    int tid = threadIdx.x;
    int lane = tid & 31, wid = tid >> 5;
    int wm = wid & 3, wn = wid >> 2;
    int grp = lane >> 2, kq = (lane & 3) * 2;

    // loader mapping: one row-half (16 floats) of A and of B per thread
    int arow = tid >> 1;
    int acol0 = (tid & 1) * 16;
    int mrow = mbase + arow;
    const float* asrc = (mrow < cnt)
        ? x + (size_t)d_tok[off + mrow] * H_DIM + acol0 : nullptr;
    int group = arow >> 5, rr = arow & 31;
    int icol = n0 + (group >> 1) * 32 + rr;
    const float* ws_e = ws + (size_t)e * (2 * I_DIM) * H_DIM;
    const float* bsrc = ws_e + (size_t)((group & 1) ? I_DIM + icol : icol) * H_DIM + acol0;

    float acc[2][8][4];
#pragma unroll
    for (int i = 0; i < 2; i++)
#pragma unroll
        for (int j = 0; j < 8; j++)
#pragma unroll
            for (int r = 0; r < 4; r++) acc[i][j][r] = 0.f;

    float4 av[4], bv[4];
#pragma unroll
    for (int q = 0; q < 4; q++) {
        av[q] = asrc ? *(const float4*)(asrc + q * 4) : make_float4(0.f, 0.f, 0.f, 0.f);
        bv[q] = *(const float4*)(bsrc + q * 4);
    }

    const int NIT = H_DIM / BK;
    for (int c = 0; c < NIT; c++) {
        __half* st = sm + (c & 1) * STG_HALF;
        sts_split(st + OFF_AH + arow * STRIDE + acol0, st + OFF_AL + arow * STRIDE + acol0, av);
        sts_split(st + OFF_BH + arow * STRIDE + acol0, st + OFF_BL + arow * STRIDE + acol0, bv);
        __syncthreads();
        if (c + 1 < NIT) {
            int k0 = (c + 1) * BK;
#pragma unroll
            for (int q = 0; q < 4; q++) {
                av[q] = asrc ? *(const float4*)(asrc + k0 + q * 4) : make_float4(0.f, 0.f, 0.f, 0.f);
                bv[q] = *(const float4*)(bsrc + k0 + q * 4);
            }
        }
        const __half* cs = sm + (c & 1) * STG_HALF;
#pragma unroll
        for (int ks = 0; ks < 2; ks++) {
            uint32_t ah[2][4], al[2][4];
#pragma unroll
            for (int i = 0; i < 2; i++) {
                const __half* p = cs + OFF_AH + (wm * 32 + i * 16 + grp) * STRIDE + ks * 16 + kq;
                ld_afrag(ah[i], p);
                ld_afrag(al[i], p + (OFF_AL - OFF_AH));
            }
#pragma unroll
            for (int j = 0; j < 8; j++) {
                const __half* pb = cs + OFF_BH + (wn * 64 + j * 8 + grp) * STRIDE + ks * 16 + kq;
                uint32_t bh0 = *(const uint32_t*)pb;
                uint32_t bh1 = *(const uint32_t*)(pb + 8);
                uint32_t bl0 = *(const uint32_t*)(pb + (OFF_BL - OFF_BH));
                uint32_t bl1 = *(const uint32_t*)(pb + (OFF_BL - OFF_BH) + 8);
#pragma unroll
                for (int i = 0; i < 2; i++) {
                    MMA16816(acc[i][j], ah[i], bh0, bh1);
                    MMA16816(acc[i][j], ah[i], bl0, bl1);
                    MMA16816(acc[i][j], al[i], bh0, bh1);
                }
            }
        }
    }

    // epilogue: fuse silu(g)*u; warp wn covers icols n0+wn*32 .. +31 (j=gate, j+4=up)
#pragma unroll
    for (int i = 0; i < 2; i++)
#pragma unroll
        for (int r = 0; r < 4; r++) {
            int m = mbase + wm * 32 + i * 16 + grp + ((r & 2) ? 8 : 0);
            if (m >= cnt) continue;
            size_t rowp = (size_t)(off + m) * I_DIM;
#pragma unroll
            for (int j = 0; j < 4; j++) {
                int ic = n0 + wn * 32 + j * 8 + kq + (r & 1);
                float g = acc[i][j][r];
                float u = acc[i][j + 4][r];
                d_h[rowp + ic] = u * g / (1.f + expf(-g));
            }
        }
}

// ---------------- 4. GEMM2: y = h @ W2^T ----------------
// grid (32, H/128, E). BM=128, BN=128, BK=32.
__global__ void __launch_bounds__(256, 1) gemm2_kernel(const float* __restrict__ w2s) {
    int e = blockIdx.z;
    int cnt = d_counts[e];
    int mbase = blockIdx.x * 128;
    if (mbase >= cnt) return;
    int off = d_offs[e];
    int n0 = blockIdx.y * 128;

    extern __shared__ __align__(16) __half sm[];

    int tid = threadIdx.x;
    int lane = tid & 31, wid = tid >> 5;
    int wm = wid & 3, wn = wid >> 2;
    int grp = lane >> 2, kq = (lane & 3) * 2;

    int arow = tid >> 1;
    int acol0 = (tid & 1) * 16;
    int mrow = mbase + arow;
    const float* asrc = (mrow < cnt)
        ? d_h + (size_t)(off + mrow) * I_DIM + acol0 : nullptr;
    const float* bsrc = w2s + (size_t)e * H_DIM * I_DIM + (size_t)(n0 + arow) * I_DIM + acol0;

    float acc[2][8][4];
#pragma unroll
    for (int i = 0; i < 2; i++)
#pragma unroll
        for (int j = 0; j < 8; j++)
#pragma unroll
            for (int r = 0; r < 4; r++) acc[i][j][r] = 0.f;

    float4 av[4], bv[4];
#pragma unroll
    for (int q = 0; q < 4; q++) {
        av[q] = asrc ? *(const float4*)(asrc + q * 4) : make_float4(0.f, 0.f, 0.f, 0.f);
        bv[q] = *(const float4*)(bsrc + q * 4);
    }

    const int NIT = I_DIM / BK;
    for (int c = 0; c < NIT; c++) {
        __half* st = sm + (c & 1) * STG_HALF;
        sts_split(st + OFF_AH + arow * STRIDE + acol0, st + OFF_AL + arow * STRIDE + acol0, av);
        sts_split(st + OFF_BH + arow * STRIDE + acol0, st + OFF_BL + arow * STRIDE + acol0, bv);
        __syncthreads();
        if (c + 1 < NIT) {
            int k0 = (c + 1) * BK;
#pragma unroll
            for (int q = 0; q < 4; q++) {
                av[q] = asrc ? *(const float4*)(asrc + k0 + q * 4) : make_float4(0.f, 0.f, 0.f, 0.f);
                bv[q] = *(const float4*)(bsrc + k0 + q * 4);
            }
        }
        const __half* cs = sm + (c & 1) * STG_HALF;
#pragma unroll
        for (int ks = 0; ks < 2; ks++) {
            uint32_t ah[2][4], al[2][4];
#pragma unroll
            for (int i = 0; i < 2; i++) {
                const __half* p = cs + OFF_AH + (wm * 32 + i * 16 + grp) * STRIDE + ks * 16 + kq;
                ld_afrag(ah[i], p);
                ld_afrag(al[i], p + (OFF_AL - OFF_AH));
            }
#pragma unroll
            for (int j = 0; j < 8; j++) {
                const __half* pb = cs + OFF_BH + (wn * 64 + j * 8 + grp) * STRIDE + ks * 16 + kq;
                uint32_t bh0 = *(const uint32_t*)pb;
                uint32_t bh1 = *(const uint32_t*)(pb + 8);
                uint32_t bl0 = *(const uint32_t*)(pb + (OFF_BL - OFF_BH));
                uint32_t bl1 = *(const uint32_t*)(pb + (OFF_BL - OFF_BH) + 8);
#pragma unroll
                for (int i = 0; i < 2; i++) {
                    MMA16816(acc[i][j], ah[i], bh0, bh1);
                    MMA16816(acc[i][j], ah[i], bl0, bl1);
                    MMA16816(acc[i][j], al[i], bh0, bh1);
                }
            }
        }
    }

#pragma unroll
    for (int i = 0; i < 2; i++)
#pragma unroll
        for (int r = 0; r < 4; r++) {
            int m = mbase + wm * 32 + i * 16 + grp + ((r & 2) ? 8 : 0);
            if (m >= cnt) continue;
            size_t rowp = (size_t)(off + m) * H_DIM;
#pragma unroll
            for (int j = 0; j < 8; j++) {
                int col = n0 + wn * 64 + j * 8 + kq + (r & 1);
                d_y[rowp + col] = acc[i][j][r];
            }
        }
}

// ---------------- 5. deterministic combine ----------------
__global__ void combine_kernel(float* __restrict__ out) {
    int idx = blockIdx.x * blockDim.x + threadIdx.x;
    int t = idx >> 11;
    int c = idx & 2047;
    float w0 = d_wts[2 * t], w1 = d_wts[2 * t + 1];
    int s0 = d_slots[2 * t], s1 = d_slots[2 * t + 1];
    out[idx] = w0 * d_y[(size_t)s0 * H_DIM + c] + w1 * d_y[(size_t)s1 * H_DIM + c];
}

// ---------------- launch ----------------
extern "C" void kernel_launch(void* const* d_in, const int* in_sizes, int n_in,
                              void* d_out, int out_size) {
    const float* x    = (const float*)d_in[0];
    const float* gw   = (const float*)d_in[1];
    const float* ws   = (const float*)d_in[2];
    const float* w2s  = (const float*)d_in[3];
    float* out = (float*)d_out;

    cudaFuncSetAttribute(gemm1_kernel, cudaFuncAttributeMaxDynamicSharedMemorySize, SMEM_BYTES);
    cudaFuncSetAttribute(gemm2_kernel, cudaFuncAttributeMaxDynamicSharedMemorySize, SMEM_BYTES);

    gate_kernel<<<T_DIM, 128>>>(x, gw);
    count_kernel<<<E_NUM, 256>>>();
    offs_kernel<<<1, 1>>>();
    fill_kernel<<<E_NUM, 256>>>();

    dim3 g1(32, I_DIM / 64, E_NUM);    // (32, 32, 16)
    gemm1_kernel<<<g1, 256, SMEM_BYTES>>>(x, ws);

    dim3 g2(32, H_DIM / 128, E_NUM);   // (32, 16, 16)
    gemm2_kernel<<<g2, 256, SMEM_BYTES>>>(w2s);

    combine_kernel<<<(T_DIM * H_DIM) / 256, 256>>>(out);
}

// round 8
// speedup vs baseline: 2.4515x; 1.2938x over previous
#include <cuda_runtime.h>
#include <cuda_fp16.h>
#include <cstdint>

#define T_DIM 4096
#define H_DIM 2048
#define I_DIM 2048
#define E_NUM 16

typedef unsigned long long ull;

// ---------------- static scratch (no allocations allowed) ----------------
__device__ int   d_ids[2 * T_DIM];
__device__ float d_wts[2 * T_DIM];
__device__ int   d_counts[E_NUM];
__device__ int   d_offs[E_NUM + 1];
__device__ int   d_tok[2 * T_DIM];
__device__ int   d_slots[2 * T_DIM];

// fp16 hi/lo preconverted operands
__device__ __half d_xh[(size_t)T_DIM * H_DIM];
__device__ __half d_xl[(size_t)T_DIM * H_DIM];
__device__ __half d_wsh[(size_t)E_NUM * 2 * I_DIM * H_DIM];   // 256 MB
__device__ __half d_wsl[(size_t)E_NUM * 2 * I_DIM * H_DIM];   // 256 MB
__device__ __half d_w2h[(size_t)E_NUM * H_DIM * I_DIM];       // 128 MB
__device__ __half d_w2l[(size_t)E_NUM * H_DIM * I_DIM];       // 128 MB
__device__ __half d_hh[(size_t)2 * T_DIM * I_DIM];
__device__ __half d_hl[(size_t)2 * T_DIM * I_DIM];
__device__ float  d_y[(size_t)2 * T_DIM * H_DIM];             // 64 MB

// ---------------- GEMM config ----------------
#define BK 32
#define STRIDE 40                        // halfs per smem row (pad -> conflict-free frags)
#define TILE_H (128 * STRIDE)            // 5120 halfs = 10240 B per tile
#define STG_HALF (4 * TILE_H)            // 20480 halfs per stage
#define STG_BYTES (STG_HALF * 2)         // 40960 B
#define OFF_AH_H 0
#define OFF_AL_H TILE_H
#define OFF_BH_H (2 * TILE_H)
#define OFF_BL_H (3 * TILE_H)
#define SMEM_BYTES (2 * STG_BYTES)       // 81920 B double-buffered

// mma.sync m16n8k16 fp16 inputs, fp32 accumulate (legacy tensor path, valid on compute_103)
#define MMA16816(d, a, b0, b1)                                              \
    asm volatile(                                                           \
        "mma.sync.aligned.m16n8k16.row.col.f32.f16.f16.f32 "                \
        "{%0,%1,%2,%3}, {%4,%5,%6,%7}, {%8,%9}, {%0,%1,%2,%3};"             \
        : "+f"((d)[0]), "+f"((d)[1]), "+f"((d)[2]), "+f"((d)[3])            \
        : "r"((a)[0]), "r"((a)[1]), "r"((a)[2]), "r"((a)[3]),               \
          "r"(b0), "r"(b1))

// cp.async helpers (16B, L2-resident)
__device__ __forceinline__ void cpa16(uint32_t dst, const void* src, int sz) {
    asm volatile("cp.async.cg.shared.global [%0], [%1], 16, %2;"
                 :: "r"(dst), "l"(src), "r"(sz));
}
#define CPA_COMMIT() asm volatile("cp.async.commit_group;" ::: "memory")
#define CPA_WAIT1()  asm volatile("cp.async.wait_group 1;" ::: "memory")
#define CPA_WAIT0()  asm volatile("cp.async.wait_group 0;" ::: "memory")

__device__ __forceinline__ uint32_t smem_u32(const void* p) {
    uint32_t a;
    asm("{ .reg .u64 t; cvta.to.shared.u64 t, %1; cvt.u32.u64 %0, t; }" : "=r"(a) : "l"(p));
    return a;
}

// split fp32 pair -> packed fp16 hi + packed fp16 lo (a = hi + lo to ~2^-22)
__device__ __forceinline__ uint32_t pack_hl(float x, float y, uint32_t& lo) {
    __half hx = __float2half_rn(x), hy = __float2half_rn(y);
    __half lx = __float2half_rn(x - __half2float(hx));
    __half ly = __float2half_rn(y - __half2float(hy));
    lo = ((uint32_t)__half_as_ushort(ly) << 16) | (uint32_t)__half_as_ushort(lx);
    return ((uint32_t)__half_as_ushort(hy) << 16) | (uint32_t)__half_as_ushort(hx);
}

// ---------------- 0. preconvert fp32 -> fp16 hi/lo (8 elems / thread) ----------------
__global__ void convert_kernel(const float4* __restrict__ src,
                               uint4* __restrict__ hi, uint4* __restrict__ lo) {
    size_t i = (size_t)blockIdx.x * blockDim.x + threadIdx.x;
    float4 v0 = src[2 * i], v1 = src[2 * i + 1];
    uint32_t h0, h1, h2, h3, l0, l1, l2, l3;
    h0 = pack_hl(v0.x, v0.y, l0);
    h1 = pack_hl(v0.z, v0.w, l1);
    h2 = pack_hl(v1.x, v1.y, l2);
    h3 = pack_hl(v1.z, v1.w, l3);
    hi[i] = make_uint4(h0, h1, h2, h3);
    lo[i] = make_uint4(l0, l1, l2, l3);
}

// ---------------- 1. gating ----------------
__global__ void gate_kernel(const float* __restrict__ x, const float* __restrict__ gw) {
    int t = blockIdx.x;
    int lane = threadIdx.x & 31;
    int w = threadIdx.x >> 5;
    const float* xr = x + (size_t)t * H_DIM;
    const float* g0 = gw + (size_t)(w * 4) * H_DIM;
    float acc0 = 0.f, acc1 = 0.f, acc2 = 0.f, acc3 = 0.f;
    for (int k = lane; k < H_DIM; k += 32) {
        float xv = xr[k];
        acc0 += xv * g0[k];
        acc1 += xv * g0[H_DIM + k];
        acc2 += xv * g0[2 * H_DIM + k];
        acc3 += xv * g0[3 * H_DIM + k];
    }
    __shared__ float sl[16];
    float accs[4] = {acc0, acc1, acc2, acc3};
#pragma unroll
    for (int j = 0; j < 4; j++) {
        float v = accs[j];
#pragma unroll
        for (int o = 16; o; o >>= 1) v += __shfl_xor_sync(0xffffffff, v, o);
        if (lane == 0) sl[w * 4 + j] = v;
    }
    __syncthreads();
    if (threadIdx.x == 0) {
        float mx = sl[0];
#pragma unroll
        for (int i = 1; i < 16; i++) mx = fmaxf(mx, sl[i]);
        float ex[16];
#pragma unroll
        for (int i = 0; i < 16; i++) ex[i] = expf(sl[i] - mx);
        int b0 = 0;
#pragma unroll
        for (int i = 1; i < 16; i++) if (sl[i] > sl[b0]) b0 = i;
        int b1 = -1;
#pragma unroll
        for (int i = 0; i < 16; i++) {
            if (i == b0) continue;
            if (b1 < 0 || sl[i] > sl[b1]) b1 = i;
        }
        float s = ex[b0] + ex[b1];
        d_ids[2 * t] = b0;
        d_ids[2 * t + 1] = b1;
        d_wts[2 * t] = ex[b0] / s;
        d_wts[2 * t + 1] = ex[b1] / s;
    }
}

// ---------------- 2. routing (parallel segmented scans, deterministic) ----------------
__global__ void count_kernel() {
    int e = blockIdx.x;
    int w = threadIdx.x >> 5, lane = threadIdx.x & 31;
    __shared__ int wcnt[8];
    int cnt = 0;
#pragma unroll
    for (int i = 0; i < 16; i++) {
        int t = w * 512 + i * 32 + lane;
        bool p = (d_ids[2 * t] == e) || (d_ids[2 * t + 1] == e);
        cnt += __popc(__ballot_sync(0xffffffff, p));
    }
    if (lane == 0) wcnt[w] = cnt;
    __syncthreads();
    if (threadIdx.x == 0) {
        int s = 0;
#pragma unroll
        for (int i = 0; i < 8; i++) s += wcnt[i];
        d_counts[e] = s;
    }
}

__global__ void offs_kernel() {
    int s = 0;
    for (int e = 0; e < E_NUM; e++) { d_offs[e] = s; s += d_counts[e]; }
    d_offs[E_NUM] = s;
}

__global__ void fill_kernel() {
    int e = blockIdx.x;
    int w = threadIdx.x >> 5, lane = threadIdx.x & 31;
    __shared__ int wcnt[8], woff[8];
    int cnt = 0;
#pragma unroll
    for (int i = 0; i < 16; i++) {
        int t = w * 512 + i * 32 + lane;
        bool p = (d_ids[2 * t] == e) || (d_ids[2 * t + 1] == e);
        cnt += __popc(__ballot_sync(0xffffffff, p));
    }
    if (lane == 0) wcnt[w] = cnt;
    __syncthreads();
    if (threadIdx.x == 0) {
        int s = 0;
#pragma unroll
        for (int i = 0; i < 8; i++) { woff[i] = s; s += wcnt[i]; }
    }
    __syncthreads();
    int pos = d_offs[e] + woff[w];
#pragma unroll
    for (int i = 0; i < 16; i++) {
        int t = w * 512 + i * 32 + lane;
        int k = (d_ids[2 * t] == e) ? 0 : ((d_ids[2 * t + 1] == e) ? 1 : -1);
        unsigned b = __ballot_sync(0xffffffff, k >= 0);
        if (k >= 0) {
            int idx = pos + __popc(b & ((1u << lane) - 1u));
            d_tok[idx] = t;
            d_slots[2 * t + k] = idx;
        }
        pos += __popc(b);
    }
}

// =========== fragment loads (conflict-free with STRIDE=40) ===========
__device__ __forceinline__ void ld_afrag(uint32_t* f, const __half* p) {
    f[0] = *(const uint32_t*)p;
    f[1] = *(const uint32_t*)(p + 8 * STRIDE);
    f[2] = *(const uint32_t*)(p + 8);
    f[3] = *(const uint32_t*)(p + 8 * STRIDE + 8);
}

// =========== shared compute core: one BK=32 stage of MMAs ===========
__device__ __forceinline__ void mma_stage(const __half* cs, int wm, int wn,
                                          int grp, int kq, float acc[2][8][4]) {
#pragma unroll
    for (int ks = 0; ks < 2; ks++) {
        uint32_t ah[2][4], al[2][4];
#pragma unroll
        for (int i = 0; i < 2; i++) {
            const __half* p = cs + OFF_AH_H + (wm * 32 + i * 16 + grp) * STRIDE + ks * 16 + kq;
            ld_afrag(ah[i], p);
            ld_afrag(al[i], p + (OFF_AL_H - OFF_AH_H));
        }
#pragma unroll
        for (int j = 0; j < 8; j++) {
            const __half* pb = cs + OFF_BH_H + (wn * 64 + j * 8 + grp) * STRIDE + ks * 16 + kq;
            uint32_t bh0 = *(const uint32_t*)pb;
            uint32_t bh1 = *(const uint32_t*)(pb + 8);
            uint32_t bl0 = *(const uint32_t*)(pb + (OFF_BL_H - OFF_BH_H));
            uint32_t bl1 = *(const uint32_t*)(pb + (OFF_BL_H - OFF_BH_H) + 8);
#pragma unroll
            for (int i = 0; i < 2; i++) {
                MMA16816(acc[i][j], ah[i], bh0, bh1);
                MMA16816(acc[i][j], ah[i], bl0, bl1);
                MMA16816(acc[i][j], al[i], bh0, bh1);
            }
        }
    }
}

// =========== shared loader: 8x cp.async 16B into stage s ===========
__device__ __forceinline__ void load_stage(uint32_t smbase, int s, int k0,
                                           int arow, int seg,
                                           const __half* aH, const __half* aL,
                                           const __half* bH, const __half* bL,
                                           int predA) {
    uint32_t d = smbase + (uint32_t)s * STG_BYTES + (uint32_t)(arow * (STRIDE * 2) + seg * 32);
    cpa16(d,                     aH + k0,     predA);
    cpa16(d + 16,                aH + k0 + 8, predA);
    cpa16(d + TILE_H * 2,        aL + k0,     predA);
    cpa16(d + TILE_H * 2 + 16,   aL + k0 + 8, predA);
    cpa16(d + 2 * TILE_H * 2,      bH + k0,     16);
    cpa16(d + 2 * TILE_H * 2 + 16, bH + k0 + 8, 16);
    cpa16(d + 3 * TILE_H * 2,      bL + k0,     16);
    cpa16(d + 3 * TILE_H * 2 + 16, bL + k0 + 8, 16);
}

// ---------------- 3. GEMM1 + fused SiLU*U -> d_hh/d_hl (fp16 hi/lo) ----------------
// grid (32, I/64, E). B rows grouped: g=row>>5, r=row&31: icol = n0+(g>>1)*32+r; g&1? up:gate
__global__ void __launch_bounds__(256, 2) gemm1_kernel() {
    int e = blockIdx.z;
    int cnt = d_counts[e];
    int mbase = blockIdx.x * 128;
    if (mbase >= cnt) return;
    int off = d_offs[e];
    int n0 = blockIdx.y * 64;

    extern __shared__ __align__(16) __half sm[];
    uint32_t smbase = smem_u32(sm);

    int tid = threadIdx.x;
    int lane = tid & 31, wid = tid >> 5;
    int wm = wid & 3, wn = wid >> 2;
    int grp = lane >> 2, kq = (lane & 3) * 2;

    int arow = tid >> 1;
    int seg = tid & 1;
    int mrow = mbase + arow;
    int predA = (mrow < cnt) ? 16 : 0;
    size_t atok = predA ? (size_t)d_tok[off + mrow] : 0;
    const __half* aH = d_xh + atok * H_DIM + seg * 16;
    const __half* aL = d_xl + atok * H_DIM + seg * 16;
    int group = arow >> 5, rr = arow & 31;
    int icol = n0 + (group >> 1) * 32 + rr;
    size_t brow = (size_t)e * (2 * I_DIM) + ((group & 1) ? I_DIM + icol : icol);
    const __half* bH = d_wsh + brow * H_DIM + seg * 16;
    const __half* bL = d_wsl + brow * H_DIM + seg * 16;

    float acc[2][8][4];
#pragma unroll
    for (int i = 0; i < 2; i++)
#pragma unroll
        for (int j = 0; j < 8; j++)
#pragma unroll
            for (int r = 0; r < 4; r++) acc[i][j][r] = 0.f;

    const int NIT = H_DIM / BK;
    load_stage(smbase, 0, 0, arow, seg, aH, aL, bH, bL, predA);
    CPA_COMMIT();
    for (int c = 0; c < NIT; c++) {
        if (c + 1 < NIT) {
            load_stage(smbase, (c + 1) & 1, (c + 1) * BK, arow, seg, aH, aL, bH, bL, predA);
            CPA_COMMIT();
            CPA_WAIT1();
        } else {
            CPA_WAIT0();
        }
        __syncthreads();
        mma_stage(sm + (c & 1) * STG_HALF, wm, wn, grp, kq, acc);
        __syncthreads();
    }

    // epilogue: silu(g)*u -> split fp16 hi/lo
#pragma unroll
    for (int i = 0; i < 2; i++)
#pragma unroll
        for (int rs = 0; rs < 2; rs++) {
            int m = mbase + wm * 32 + i * 16 + grp + rs * 8;
            if (m >= cnt) continue;
            size_t rowp = (size_t)(off + m) * I_DIM;
#pragma unroll
            for (int j = 0; j < 4; j++) {
                int ic = n0 + wn * 32 + j * 8 + kq;
                float g0 = acc[i][j][rs * 2],     g1 = acc[i][j][rs * 2 + 1];
                float u0 = acc[i][j + 4][rs * 2], u1 = acc[i][j + 4][rs * 2 + 1];
                float h0 = u0 * g0 / (1.f + expf(-g0));
                float h1 = u1 * g1 / (1.f + expf(-g1));
                __half hh0 = __float2half_rn(h0);
                __half hh1 = __float2half_rn(h1);
                __half hl0 = __float2half_rn(h0 - __half2float(hh0));
                __half hl1 = __float2half_rn(h1 - __half2float(hh1));
                *(__half2*)(d_hh + rowp + ic) = __halves2half2(hh0, hh1);
                *(__half2*)(d_hl + rowp + ic) = __halves2half2(hl0, hl1);
            }
        }
}

// ---------------- 4. GEMM2: y = h @ W2^T -> d_y ----------------
// grid (32, H/128, E). BM=128, BN=128, BK=32.
__global__ void __launch_bounds__(256, 2) gemm2_kernel() {
    int e = blockIdx.z;
    int cnt = d_counts[e];
    int mbase = blockIdx.x * 128;
    if (mbase >= cnt) return;
    int off = d_offs[e];
    int n0 = blockIdx.y * 128;

    extern __shared__ __align__(16) __half sm[];
    uint32_t smbase = smem_u32(sm);

    int tid = threadIdx.x;
    int lane = tid & 31, wid = tid >> 5;
    int wm = wid & 3, wn = wid >> 2;
    int grp = lane >> 2, kq = (lane & 3) * 2;

    int arow = tid >> 1;
    int seg = tid & 1;
    int mrow = mbase + arow;
    int predA = (mrow < cnt) ? 16 : 0;
    size_t aoff = predA ? (size_t)(off + mrow) : 0;
    const __half* aH = d_hh + aoff * I_DIM + seg * 16;
    const __half* aL = d_hl + aoff * I_DIM + seg * 16;
    size_t brow = (size_t)e * H_DIM + (n0 + arow);
    const __half* bH = d_w2h + brow * I_DIM + seg * 16;
    const __half* bL = d_w2l + brow * I_DIM + seg * 16;

    float acc[2][8][4];
#pragma unroll
    for (int i = 0; i < 2; i++)
#pragma unroll
        for (int j = 0; j < 8; j++)
#pragma unroll
            for (int r = 0; r < 4; r++) acc[i][j][r] = 0.f;

    const int NIT = I_DIM / BK;
    load_stage(smbase, 0, 0, arow, seg, aH, aL, bH, bL, predA);
    CPA_COMMIT();
    for (int c = 0; c < NIT; c++) {
        if (c + 1 < NIT) {
            load_stage(smbase, (c + 1) & 1, (c + 1) * BK, arow, seg, aH, aL, bH, bL, predA);
            CPA_COMMIT();
            CPA_WAIT1();
        } else {
            CPA_WAIT0();
        }
        __syncthreads();
        mma_stage(sm + (c & 1) * STG_HALF, wm, wn, grp, kq, acc);
        __syncthreads();
    }

#pragma unroll
    for (int i = 0; i < 2; i++)
#pragma unroll
        for (int rs = 0; rs < 2; rs++) {
            int m = mbase + wm * 32 + i * 16 + grp + rs * 8;
            if (m >= cnt) continue;
            size_t rowp = (size_t)(off + m) * H_DIM;
#pragma unroll
            for (int j = 0; j < 8; j++) {
                int col = n0 + wn * 64 + j * 8 + kq;
                *(float2*)(d_y + rowp + col) =
                    make_float2(acc[i][j][rs * 2], acc[i][j][rs * 2 + 1]);
            }
        }
}

// ---------------- 5. deterministic combine ----------------
__global__ void combine_kernel(float* __restrict__ out) {
    int idx = blockIdx.x * blockDim.x + threadIdx.x;
    int t = idx >> 11;
    int c = idx & 2047;
    float w0 = d_wts[2 * t], w1 = d_wts[2 * t + 1];
    int s0 = d_slots[2 * t], s1 = d_slots[2 * t + 1];
    out[idx] = w0 * d_y[(size_t)s0 * H_DIM + c] + w1 * d_y[(size_t)s1 * H_DIM + c];
}

// ---------------- launch ----------------
extern "C" void kernel_launch(void* const* d_in, const int* in_sizes, int n_in,
                              void* d_out, int out_size) {
    const float* x    = (const float*)d_in[0];
    const float* gw   = (const float*)d_in[1];
    const float* ws   = (const float*)d_in[2];
    const float* w2s  = (const float*)d_in[3];
    float* out = (float*)d_out;

    cudaFuncSetAttribute(gemm1_kernel, cudaFuncAttributeMaxDynamicSharedMemorySize, SMEM_BYTES);
    cudaFuncSetAttribute(gemm2_kernel, cudaFuncAttributeMaxDynamicSharedMemorySize, SMEM_BYTES);

    // preconvert operands to fp16 hi/lo (grid = n/8/256)
    __half *xh, *xl, *wsh, *wsl, *w2h, *w2l;
    cudaGetSymbolAddress((void**)&xh,  d_xh);
    cudaGetSymbolAddress((void**)&xl,  d_xl);
    cudaGetSymbolAddress((void**)&wsh, d_wsh);
    cudaGetSymbolAddress((void**)&wsl, d_wsl);
    cudaGetSymbolAddress((void**)&w2h, d_w2h);
    cudaGetSymbolAddress((void**)&w2l, d_w2l);

    convert_kernel<<<4096, 256>>>((const float4*)x, (uint4*)xh, (uint4*)xl);
    convert_kernel<<<65536, 256>>>((const float4*)ws, (uint4*)wsh, (uint4*)wsl);
    convert_kernel<<<32768, 256>>>((const float4*)w2s, (uint4*)w2h, (uint4*)w2l);

    gate_kernel<<<T_DIM, 128>>>(x, gw);
    count_kernel<<<E_NUM, 256>>>();
    offs_kernel<<<1, 1>>>();
    fill_kernel<<<E_NUM, 256>>>();

    dim3 g1(32, I_DIM / 64, E_NUM);    // (32, 32, 16)
    gemm1_kernel<<<g1, 256, SMEM_BYTES>>>();

    dim3 g2(32, H_DIM / 128, E_NUM);   // (32, 16, 16)
    gemm2_kernel<<<g2, 256, SMEM_BYTES>>>();

    combine_kernel<<<(T_DIM * H_DIM) / 256, 256>>>(out);
}